// round 11
// baseline (speedup 1.0000x reference)
#include <cuda_runtime.h>

// GraphPyramidPooling — adjacency (d_in[0]) is dead code. Live math:
//   s0 = sig(h·w0+b0); s1 = sig(s0*(h·w1)+b1); s2 = sig((s0*s1)*(h·w2)+b2)
//   out[r] = a0[r]*h[r] + g1[r]*h[src1[r]] + g2[r]*h[src2[r]]
// exact stable top-k per level via u64 keys (bits(score)<<32 | ~pos).
//
// R10: 4 launches. rank1+rank2 fused: every rank1 block stages all level-1
// keys anyway, so it computes T1 (K1-th largest k1, exact in-block MSD radix
// select; keys unique -> early exit) and evaluates mask1(j) = k1_j >= T1 on
// the fly. Level-2 ties (by rank1 order) reuse the k1 comparison, so rank2
// is counted in the same scan: exact, no extra kernel.

#define D   512
#define DV  (D/4)
#define N0  4096
#define K0  3276
#define N1  3276
#define K1  1965
#define K2  786
#define NP0 4096
#define NP1 3328   // 3276 padded

#define RNB 148
#define RNT 512
#define RNW (RNB * 16)   // 2368 warps

typedef unsigned long long u64;
typedef unsigned int u32;

__device__ u64   g_k0[NP0];
__device__ u64   g_k1[N1];
__device__ u32   g_s2lv[N1];
__device__ float g_s0a[N0];
__device__ float g_s1a[N0];
__device__ u32   g_s2a[N0];
__device__ float g_a0[N0];
__device__ float g_g1[N1];
__device__ int   g_src1[N1];
__device__ float g_g2[K1];
__device__ int   g_src2[K1];
__device__ int   g_inv0[N1];

__device__ __forceinline__ float warp_sum(float v) {
#pragma unroll
    for (int o = 16; o; o >>= 1) v += __shfl_xor_sync(0xffffffffu, v, o);
    return v;
}
__device__ __forceinline__ float sigmoidf(float x) {
    return 1.0f / (1.0f + expf(-x));
}
__device__ __forceinline__ u64 make_key(float s, int idx) {
    return ((u64)(u32)__float_as_int(s) << 32) | (u32)(~(u32)idx);
}
__device__ __forceinline__ float key_score(u64 k) {
    return __int_as_float((int)(k >> 32));
}

// L1: one warp per row; 3 dots; all three per-row scores.
__global__ void pass_a(const float* __restrict__ h,
                       const float* __restrict__ W,
                       const float* __restrict__ b) {
    int w    = (blockIdx.x * blockDim.x + threadIdx.x) >> 5;
    int lane = threadIdx.x & 31;
    if (w >= N0) return;
    const float4* hr = (const float4*)h + (size_t)w * DV;
    const float4* w0 = (const float4*)W;
    const float4* w1 = w0 + DV;
    const float4* w2 = w0 + 2 * DV;
    float a0 = 0.f, a1 = 0.f, a2 = 0.f;
#pragma unroll
    for (int i = 0; i < 4; i++) {
        float4 a  = __ldg(hr + lane + 32 * i);
        float4 c0 = __ldg(w0 + lane + 32 * i);
        float4 c1 = __ldg(w1 + lane + 32 * i);
        float4 c2 = __ldg(w2 + lane + 32 * i);
        a0 += a.x * c0.x + a.y * c0.y + a.z * c0.z + a.w * c0.w;
        a1 += a.x * c1.x + a.y * c1.y + a.z * c1.z + a.w * c1.w;
        a2 += a.x * c2.x + a.y * c2.y + a.z * c2.z + a.w * c2.w;
    }
    a0 = warp_sum(a0); a1 = warp_sum(a1); a2 = warp_sum(a2);
    if (lane == 0) {
        float s0 = sigmoidf(a0 + b[0]);
        float s1 = sigmoidf(s0 * a1 + b[1]);
        float s2 = sigmoidf((s0 * s1) * a2 + b[2]);
        g_s0a[w] = s0;
        g_s1a[w] = s1;
        g_s2a[w] = (u32)__float_as_int(s2);
        g_k0[w]  = make_key(s0, w);
    }
}

// L2: exact stable rank0 for all rows; scatter level-1 keys + s2 + inv map.
__global__ void __launch_bounds__(RNT) rank0_kernel() {
    __shared__ __align__(16) u64 smk[NP0];
    for (int t = threadIdx.x; t < NP0 / 2; t += RNT)
        ((ulonglong2*)smk)[t] = __ldg((const ulonglong2*)g_k0 + t);
    __syncthreads();

    const int wid  = threadIdx.x >> 5;
    const int lane = threadIdx.x & 31;
    const int gw   = blockIdx.x * 16 + wid;
    const int i1 = gw, i2 = gw + RNW;   // both < N0 = 4096 (2368*2 > 4096 ok)

    u64 kA = (i1 < N0) ? smk[i1] : ~0ULL;
    u64 kB = (i2 < N0) ? smk[i2] : ~0ULL;
    int ca = 0, cb = 0;
    const ulonglong2* s2p = (const ulonglong2*)smk;
#pragma unroll 4
    for (int q = lane; q < NP0 / 2; q += 32) {
        ulonglong2 v = s2p[q];
        ca += (int)(v.x > kA) + (int)(v.y > kA);
        cb += (int)(v.x > kB) + (int)(v.y > kB);
    }
    int packed = ca | (cb << 16);
#pragma unroll
    for (int o = 16; o; o >>= 1) packed += __shfl_xor_sync(0xffffffffu, packed, o);
    if (lane != 0) return;

#pragma unroll
    for (int t = 0; t < 2; t++) {
        const int i = (t == 0) ? i1 : i2;
        if (i >= N0) continue;
        const int rank = (t == 0) ? (packed & 0xFFFF) : (packed >> 16);
        const u64 k = (t == 0) ? kA : kB;
        const bool sel = rank < K0;
        float s0 = key_score(k);
        g_a0[i] = sel ? s0 : 0.f;
        if (sel) {
            g_k1[rank]   = make_key(g_s1a[i], rank);
            g_s2lv[rank] = g_s2a[i];
            g_inv0[rank] = i;
        }
    }
}

// L3: fused rank1+rank2. Stage k1 + s2; in-block exact MSD radix select for
// T1 = K1-th largest k1 (mask1(j) = k1_j >= T1); one scan counts both ranks.
__global__ void __launch_bounds__(RNT) rank12_kernel() {
    __shared__ __align__(16) u64 smk[NP1];
    __shared__ __align__(16) u32 sms[NP1];
    __shared__ u32 hist[256], sfx[256];
    __shared__ int ctl[2];
    __shared__ u64 s_thr;
    __shared__ int s_done;

    const int tid = threadIdx.x;
    for (int t = tid; t < NP1; t += RNT) {
        smk[t] = (t < N1) ? __ldg(g_k1 + t) : 0ULL;     // pad < all real keys
        sms[t] = (t < N1) ? __ldg(g_s2lv + t) : 0u;
    }
    if (tid == 0) s_done = 0;
    __syncthreads();

    // ---- exact MSD radix select: T1 = K1-th largest of smk ----
    {
        u64 prefix = 0, pmask = 0;
        int want = K1;
        for (int shift = 56; shift >= 0; shift -= 8) {
            if (s_done) break;
            for (int t = tid; t < 256; t += RNT) hist[t] = 0;
            __syncthreads();
            for (int j = tid; j < NP1; j += RNT) {
                u64 k = smk[j];
                if (((k ^ prefix) & pmask) == 0)
                    atomicAdd(&hist[(u32)(k >> shift) & 255], 1u);
            }
            __syncthreads();
            for (int t = tid; t < 256; t += RNT) sfx[t] = hist[t];
            __syncthreads();
            for (int off = 1; off < 256; off <<= 1) {   // suffix sums
                u32 v = 0;
                if (tid < 256 && tid + off < 256) v = sfx[tid + off];
                __syncthreads();
                if (tid < 256) sfx[tid] += v;
                __syncthreads();
            }
            if (tid < 256) {
                int ge = (int)sfx[tid];
                int gt = ge - (int)hist[tid];
                if (gt < want && want <= ge) { ctl[0] = tid; ctl[1] = want - gt; }
            }
            __syncthreads();
            int bin = ctl[0];
            int cnt = (int)hist[bin];
            want    = ctl[1];
            prefix |= ((u64)(u32)bin) << shift;
            pmask  |= ((u64)255) << shift;
            __syncthreads();
            if (cnt == 1) {   // unique candidate: it IS the threshold
                for (int j = tid; j < NP1; j += RNT) {
                    u64 k = smk[j];
                    if (((k ^ pmask) & pmask) == ((prefix ^ pmask) & pmask) &&
                        ((k ^ prefix) & pmask) == 0) { s_thr = k; s_done = 1; }
                }
                __syncthreads();
            }
        }
        if (!s_done && tid == 0) s_thr = prefix;  // all 8 bytes resolved
        __syncthreads();
    }
    const u64 T1 = s_thr;

    // ---- scan: rank1 (strict k1 >) and rank2 ((s2, k1-order) lex, mask1) ----
    const int wid  = tid >> 5;
    const int lane = tid & 31;
    const int gw   = blockIdx.x * 16 + wid;
    const int i1 = gw, i2 = gw + RNW;

    u64 kA = (i1 < N1) ? smk[i1] : ~0ULL;
    u64 kB = (i2 < N1) ? smk[i2] : ~0ULL;
    u32 sA = (i1 < N1) ? sms[i1] : 0xFFFFFFFFu;
    u32 sB = (i2 < N1) ? sms[i2] : 0xFFFFFFFFu;
    int c1a = 0, c1b = 0, c2a = 0, c2b = 0;
    const ulonglong2* k2p = (const ulonglong2*)smk;
    const uint2*      s2q = (const uint2*)sms;
#pragma unroll 4
    for (int q = lane; q < NP1 / 2; q += 32) {
        ulonglong2 kv = k2p[q];
        uint2      sv = s2q[q];
        int m1x = kv.x >= T1, m1y = kv.y >= T1;
        int gAx = kv.x > kA,  gAy = kv.y > kA;
        int gBx = kv.x > kB,  gBy = kv.y > kB;
        c1a += gAx + gAy;
        c1b += gBx + gBy;
        c2a += (m1x & ((sv.x > sA) | ((sv.x == sA) & gAx)))
             + (m1y & ((sv.y > sA) | ((sv.y == sA) & gAy)));
        c2b += (m1x & ((sv.x > sB) | ((sv.x == sB) & gBx)))
             + (m1y & ((sv.y > sB) | ((sv.y == sB) & gBy)));
    }
    int p1 = c1a | (c1b << 16);
    int p2 = c2a | (c2b << 16);
#pragma unroll
    for (int o = 16; o; o >>= 1) {
        p1 += __shfl_xor_sync(0xffffffffu, p1, o);
        p2 += __shfl_xor_sync(0xffffffffu, p2, o);
    }
    if (lane != 0) return;

#pragma unroll
    for (int t = 0; t < 2; t++) {
        const int i = (t == 0) ? i1 : i2;
        if (i >= N1) continue;
        const int r1 = (t == 0) ? (p1 & 0xFFFF) : (p1 >> 16);
        const int r2 = (t == 0) ? (p2 & 0xFFFF) : (p2 >> 16);
        const u64 k  = (t == 0) ? kA : kB;
        const u32 s2b = (t == 0) ? sA : sB;
        const bool sel1 = r1 < K1;
        int   src  = g_inv0[i];
        float s1   = key_score(k);
        float gain = g_s0a[src] * s1;
        g_g1[i]   = sel1 ? gain : 0.f;
        g_src1[i] = src;
        if (sel1) {
            float s2 = __uint_as_float((int)s2b);
            g_g2[r1]   = (r2 < K2) ? gain * s2 : 0.f;
            g_src2[r1] = src;
        }
    }
}

// L4: out[r] = a0*h[r] + g1*h[src1] + g2*h[src2]. 1 thread per float4.
__global__ void __launch_bounds__(512)
final_kernel(const float* __restrict__ h, float* __restrict__ out) {
    int tid = blockIdx.x * 512 + threadIdx.x;   // 0 .. N0*DV-1
    int r = tid >> 7;
    int c = tid & 127;
    const float4* h4 = (const float4*)h;
    float a0 = __ldg(g_a0 + r);
    float4 v0 = __ldg(h4 + (size_t)r * DV + c);
    float4 o;
    o.x = a0 * v0.x; o.y = a0 * v0.y; o.z = a0 * v0.z; o.w = a0 * v0.w;
    if (r < K0) {
        float g1 = __ldg(g_g1 + r);
        int   s1 = __ldg(g_src1 + r);
        float4 v1 = __ldg(h4 + (size_t)s1 * DV + c);
        o.x += g1 * v1.x; o.y += g1 * v1.y; o.z += g1 * v1.z; o.w += g1 * v1.w;
        if (r < K1) {
            float g2 = __ldg(g_g2 + r);
            int   s2 = __ldg(g_src2 + r);
            float4 v2 = __ldg(h4 + (size_t)s2 * DV + c);
            o.x += g2 * v2.x; o.y += g2 * v2.y; o.z += g2 * v2.z; o.w += g2 * v2.w;
        }
    }
    ((float4*)out)[tid] = o;
}

extern "C" void kernel_launch(void* const* d_in, const int* in_sizes, int n_in,
                              void* d_out, int out_size) {
    // inputs: [0]=g (UNUSED), [1]=h [4096,512], [2]=W [3,512], [3]=b [3]
    const float* h = (const float*)d_in[1];
    const float* W = (const float*)d_in[2];
    const float* b = (const float*)d_in[3];
    float* out = (float*)d_out;

    pass_a<<<N0 / 8, 256>>>(h, W, b);
    rank0_kernel<<<RNB, RNT>>>();
    rank12_kernel<<<RNB, RNT>>>();
    final_kernel<<<(N0 * DV) / 512, 512>>>(h, out);
}

// round 12
// speedup vs baseline: 1.1417x; 1.1417x over previous
#include <cuda_runtime.h>

// GraphPyramidPooling — adjacency (d_in[0]) is dead code. Live math:
//   s0 = sig(h·w0+b0); s1 = sig(s0*(h·w1)+b1); s2 = sig((s0*s1)*(h·w2)+b2)
//   out[r] = a0[r]*h[r] + g1[r]*h[src1[r]] + g2[r]*h[src2[r]]
// exact stable top-k per level via u64 keys (bits(score)<<32 | ~pos).
//
// R11: 4 launches. rank2's counting scan replaced by a THRESHOLD: level-2
// keys k2 = (s2<<32|~rank1) are unique, so sel2(r) = k2[r] >= T2 with
// T2 = K2-th largest. Final-kernel blocks that own rows < K1 compute T2
// redundantly via an exact in-block MSD radix select (16KB smem, ~3 rounds,
// early exit); everything else is the verified R9/R10 pipeline.

#define D   512
#define DV  (D/4)
#define N0  4096
#define K0  3276
#define N1  3276
#define K1  1965
#define K2  786
#define NP0 4096
#define NP1 3328

#define RNB 148
#define RNT 512
#define RNW (RNB * 16)   // 2368 warps
#define FNT 512
#define FNB ((N0 * DV / 2) / FNT)   // 512 blocks, 2 float4 per thread

typedef unsigned long long u64;
typedef unsigned int u32;

__device__ u64   g_k0[NP0];
__device__ u64   g_k1[N1];
__device__ u32   g_s2lv[N1];    // s2 bits at level-1 positions
__device__ float g_s0a[N0];
__device__ float g_s1a[N0];
__device__ u32   g_s2a[N0];
__device__ float g_a0[N0];
__device__ float g_g1[K0];
__device__ int   g_src1[K0];
__device__ u64   g_k2lv[K1];    // (s2<<32 | ~rank1) at level-2 positions
__device__ float g_gain2[K1];   // s0*s1*s2 (value if selected)
__device__ int   g_src2[K1];
__device__ int   g_inv0[N1];

__device__ __forceinline__ float warp_sum(float v) {
#pragma unroll
    for (int o = 16; o; o >>= 1) v += __shfl_xor_sync(0xffffffffu, v, o);
    return v;
}
__device__ __forceinline__ float sigmoidf(float x) {
    return 1.0f / (1.0f + expf(-x));
}
__device__ __forceinline__ u64 make_key(float s, int idx) {
    return ((u64)(u32)__float_as_int(s) << 32) | (u32)(~(u32)idx);
}
__device__ __forceinline__ float key_score(u64 k) {
    return __int_as_float((int)(k >> 32));
}

// K1: one warp per row; 3 dots; all three per-row scores (verified R10).
__global__ void pass_a(const float* __restrict__ h,
                       const float* __restrict__ W,
                       const float* __restrict__ b) {
    int w    = (blockIdx.x * blockDim.x + threadIdx.x) >> 5;
    int lane = threadIdx.x & 31;
    if (w >= N0) return;
    const float4* hr = (const float4*)h + (size_t)w * DV;
    const float4* w0 = (const float4*)W;
    const float4* w1 = w0 + DV;
    const float4* w2 = w0 + 2 * DV;
    float a0 = 0.f, a1 = 0.f, a2 = 0.f;
#pragma unroll
    for (int i = 0; i < 4; i++) {
        float4 a  = __ldg(hr + lane + 32 * i);
        float4 c0 = __ldg(w0 + lane + 32 * i);
        float4 c1 = __ldg(w1 + lane + 32 * i);
        float4 c2 = __ldg(w2 + lane + 32 * i);
        a0 += a.x * c0.x + a.y * c0.y + a.z * c0.z + a.w * c0.w;
        a1 += a.x * c1.x + a.y * c1.y + a.z * c1.z + a.w * c1.w;
        a2 += a.x * c2.x + a.y * c2.y + a.z * c2.z + a.w * c2.w;
    }
    a0 = warp_sum(a0); a1 = warp_sum(a1); a2 = warp_sum(a2);
    if (lane == 0) {
        float s0 = sigmoidf(a0 + b[0]);
        float s1 = sigmoidf(s0 * a1 + b[1]);
        float s2 = sigmoidf((s0 * s1) * a2 + b[2]);
        g_s0a[w] = s0;
        g_s1a[w] = s1;
        g_s2a[w] = (u32)__float_as_int(s2);
        g_k0[w]  = make_key(s0, w);
    }
}

// K2: exact stable rank0; scatter level-1 keys + s2 + inverse map (verified R10).
__global__ void __launch_bounds__(RNT) rank0_kernel() {
    __shared__ __align__(16) u64 smk[NP0];
    for (int t = threadIdx.x; t < NP0 / 2; t += RNT)
        ((ulonglong2*)smk)[t] = __ldg((const ulonglong2*)g_k0 + t);
    __syncthreads();

    const int wid  = threadIdx.x >> 5;
    const int lane = threadIdx.x & 31;
    const int gw   = blockIdx.x * 16 + wid;
    const int i1 = gw, i2 = gw + RNW;

    u64 kA = (i1 < N0) ? smk[i1] : ~0ULL;
    u64 kB = (i2 < N0) ? smk[i2] : ~0ULL;
    int ca = 0, cb = 0;
    const ulonglong2* s2p = (const ulonglong2*)smk;
#pragma unroll 4
    for (int q = lane; q < NP0 / 2; q += 32) {
        ulonglong2 v = s2p[q];
        ca += (int)(v.x > kA) + (int)(v.y > kA);
        cb += (int)(v.x > kB) + (int)(v.y > kB);
    }
    int packed = ca | (cb << 16);
#pragma unroll
    for (int o = 16; o; o >>= 1) packed += __shfl_xor_sync(0xffffffffu, packed, o);
    if (lane != 0) return;

#pragma unroll
    for (int t = 0; t < 2; t++) {
        const int i = (t == 0) ? i1 : i2;
        if (i >= N0) continue;
        const int rank = (t == 0) ? (packed & 0xFFFF) : (packed >> 16);
        const u64 k = (t == 0) ? kA : kB;
        const bool sel = rank < K0;
        float s0 = key_score(k);
        g_a0[i] = sel ? s0 : 0.f;
        if (sel) {
            g_k1[rank]   = make_key(g_s1a[i], rank);
            g_s2lv[rank] = g_s2a[i];
            g_inv0[rank] = i;
        }
    }
}

// K3: exact stable rank1 over level-1 keys; scatter gains + level-2 keys.
__global__ void __launch_bounds__(RNT) rank1_kernel() {
    __shared__ __align__(16) u64 smk[NP1];
    const ulonglong2* gk2 = (const ulonglong2*)g_k1;
    for (int t = threadIdx.x; t < NP1 / 2; t += RNT) {
        ulonglong2 v;
        if (2 * t + 1 < N1) v = __ldg(gk2 + t);
        else { v.x = (2 * t < N1) ? __ldg(g_k1 + 2 * t) : 0ULL; v.y = 0ULL; }
        ((ulonglong2*)smk)[t] = v;
    }
    __syncthreads();

    const int wid  = threadIdx.x >> 5;
    const int lane = threadIdx.x & 31;
    const int gw   = blockIdx.x * 16 + wid;
    const int i1 = gw, i2 = gw + RNW;

    u64 kA = (i1 < N1) ? smk[i1] : ~0ULL;
    u64 kB = (i2 < N1) ? smk[i2] : ~0ULL;
    int ca = 0, cb = 0;
    const ulonglong2* s2p = (const ulonglong2*)smk;
#pragma unroll 4
    for (int q = lane; q < NP1 / 2; q += 32) {
        ulonglong2 v = s2p[q];
        ca += (int)(v.x > kA) + (int)(v.y > kA);
        cb += (int)(v.x > kB) + (int)(v.y > kB);
    }
    int packed = ca | (cb << 16);
#pragma unroll
    for (int o = 16; o; o >>= 1) packed += __shfl_xor_sync(0xffffffffu, packed, o);
    if (lane != 0) return;

#pragma unroll
    for (int t = 0; t < 2; t++) {
        const int p = (t == 0) ? i1 : i2;
        if (p >= N1) continue;
        const int r1 = (t == 0) ? (packed & 0xFFFF) : (packed >> 16);
        const u64 k  = (t == 0) ? kA : kB;
        const bool sel1 = r1 < K1;
        int   src  = g_inv0[p];
        float s1   = key_score(k);
        float gain = g_s0a[src] * s1;
        g_g1[p]   = sel1 ? gain : 0.f;
        g_src1[p] = src;
        if (sel1) {
            float s2 = __uint_as_float((int)g_s2lv[p]);
            g_k2lv[r1]  = make_key(s2, r1);
            g_gain2[r1] = gain * s2;
            g_src2[r1]  = src;
        }
    }
}

// Exact MSD radix select: 'want'-th largest of keys[0..n). Keys unique ->
// early exit guaranteed (latest at byte 0). Warp-0 suffix scan, 3 syncs/round.
__device__ u64 select_topk(const u64* keys, int n, int want,
                           u32* hist, int* ctl, u64* s_thr) {
    const int tid = threadIdx.x;
    u64 prefix = 0, pmask = 0;
    for (int shift = 56; shift >= 0; shift -= 8) {
        if (tid < 256) hist[tid] = 0;
        __syncthreads();
        for (int j = tid; j < n; j += blockDim.x) {
            u64 k = keys[j];
            if (((k ^ prefix) & pmask) == 0)
                atomicAdd(&hist[(u32)(k >> shift) & 255], 1u);
        }
        __syncthreads();
        if (tid < 32) {
            u32 hh[8]; u32 lsum = 0;
#pragma unroll
            for (int q = 0; q < 8; q++) { hh[q] = hist[tid * 8 + q]; lsum += hh[q]; }
            u32 suf = lsum;   // inclusive suffix across lanes (hi lanes = hi digits)
#pragma unroll
            for (int o = 1; o < 32; o <<= 1) {
                u32 v = __shfl_down_sync(0xffffffffu, suf, o);
                if (tid + o < 32) suf += v;
            }
            u32 run = suf - lsum;   // keys in strictly-higher lanes
            for (int q = 7; q >= 0; q--) {
                u32 ge = run + hh[q];
                if ((int)run < want && want <= (int)ge) {
                    ctl[0] = tid * 8 + q;
                    ctl[1] = want - (int)run;
                    ctl[2] = (int)hh[q];
                }
                run = ge;
            }
        }
        __syncthreads();
        int bin = ctl[0];
        want    = ctl[1];
        int cnt = ctl[2];
        prefix |= ((u64)(u32)bin) << shift;
        pmask  |= 255ULL << shift;
        if (cnt == 1) {
            for (int j = tid; j < n; j += blockDim.x) {
                u64 k = keys[j];
                if (((k ^ prefix) & pmask) == 0) *s_thr = k;
            }
            __syncthreads();
            return *s_thr;
        }
    }
    return prefix;   // fully resolved (only reachable with duplicate keys)
}

// K4: T2 select (blocks owning rows < K1) + gather.
// out[r] = a0*h[r] + g1*h[src1] + (k2[r]>=T2 ? gain2[r] : 0)*h[src2].
__global__ void __launch_bounds__(FNT)
final_kernel(const float* __restrict__ h, float* __restrict__ out) {
    __shared__ __align__(16) u64 smk2[K1 + 3];
    __shared__ u32 hist[256];
    __shared__ int ctl[3];
    __shared__ u64 s_thr;

    const int tid  = threadIdx.x;
    const int row0 = blockIdx.x * (FNT / 64);   // 8 rows per block
    u64 T2 = 0;
    if (row0 < K1) {
        for (int t = tid; t < K1; t += FNT) smk2[t] = __ldg(g_k2lv + t);
        __syncthreads();
        T2 = select_topk(smk2, K1, K2, hist, ctl, &s_thr);
    }

    const int gtid = blockIdx.x * FNT + tid;    // 0 .. N0*DV/2-1
    const int r = gtid >> 6;
    const int c = gtid & 63;
    const float4* h4 = (const float4*)h;
    float a0 = __ldg(g_a0 + r);
    float4 va = __ldg(h4 + (size_t)r * DV + c);
    float4 vb = __ldg(h4 + (size_t)r * DV + c + 64);
    float4 oa, ob;
    oa.x = a0 * va.x; oa.y = a0 * va.y; oa.z = a0 * va.z; oa.w = a0 * va.w;
    ob.x = a0 * vb.x; ob.y = a0 * vb.y; ob.z = a0 * vb.z; ob.w = a0 * vb.w;
    if (r < K0) {
        float g1 = __ldg(g_g1 + r);
        int   s1 = __ldg(g_src1 + r);
        float4 wa = __ldg(h4 + (size_t)s1 * DV + c);
        float4 wb = __ldg(h4 + (size_t)s1 * DV + c + 64);
        oa.x += g1 * wa.x; oa.y += g1 * wa.y; oa.z += g1 * wa.z; oa.w += g1 * wa.w;
        ob.x += g1 * wb.x; ob.y += g1 * wb.y; ob.z += g1 * wb.z; ob.w += g1 * wb.w;
        if (r < K1) {
            u64 k2 = smk2[r - row0 * 0 + 0 * r];   // placeholder avoided; see below
            k2 = __ldg(g_k2lv + r);
            float g2 = (k2 >= T2) ? __ldg(g_gain2 + r) : 0.f;
            int   s2 = __ldg(g_src2 + r);
            float4 ua = __ldg(h4 + (size_t)s2 * DV + c);
            float4 ub = __ldg(h4 + (size_t)s2 * DV + c + 64);
            oa.x += g2 * ua.x; oa.y += g2 * ua.y; oa.z += g2 * ua.z; oa.w += g2 * ua.w;
            ob.x += g2 * ub.x; ob.y += g2 * ub.y; ob.z += g2 * ub.z; ob.w += g2 * ub.w;
        }
    }
    ((float4*)out)[(size_t)r * DV + c]      = oa;
    ((float4*)out)[(size_t)r * DV + c + 64] = ob;
}

extern "C" void kernel_launch(void* const* d_in, const int* in_sizes, int n_in,
                              void* d_out, int out_size) {
    // inputs: [0]=g (UNUSED), [1]=h [4096,512], [2]=W [3,512], [3]=b [3]
    const float* h = (const float*)d_in[1];
    const float* W = (const float*)d_in[2];
    const float* b = (const float*)d_in[3];
    float* out = (float*)d_out;

    pass_a<<<N0 / 8, 256>>>(h, W, b);
    rank0_kernel<<<RNB, RNT>>>();
    rank1_kernel<<<RNB, RNT>>>();
    final_kernel<<<FNB, FNT>>>(h, out);
}